// round 15
// baseline (speedup 1.0000x reference)
#include <cuda_runtime.h>
#include <cstdint>

// ---------------------------------------------------------------------------
// MultiLoss_JSD: fused MSE + 17-head CE + histogram JSD
// B = 262144 rows; decoded/true: [B,168] f32; encoded: [B,11] f32; label: [B,1] f32
// out: 4 floats [multi, mse, ce, 0.1*kld]
//
// Single fused kernel + finalize:
//   blocks [0, PREPB):        phase1 minmax+male -> grid-subset sync -> phase2 hist
//   blocks [PREPB, +mainb):   CE+MSE cp.async streaming
// Prep blocks are FIRST in the grid => all co-resident in wave 1 => spin is safe.
// ---------------------------------------------------------------------------

#define NSLICE 17
#define NBINS  800
#define NCOLS  168
#define NF4    42          // float4s per row
#define NF     2           // float4s per chunk per row
#define NCH    21          // 21 chunks * 8 cols = 168
#define STAGES 3
#define ROWS_PB 128
#define RATIO_JSD 0.1
#define FIN_BLOCKS 16
#define HB_PER_SEX 256
#define PREPB (2 * HB_PER_SEX)       // 512 prep blocks (minmax then hist)

#define PIPE_BYTES (STAGES * ROWS_PB * NF * 16 * 2)   // 24576
#define HALF_PIPE  (STAGES * ROWS_PB * NF * 16)       // 12288

__host__ __device__ constexpr int slice_of(int c) {
    const int S[NSLICE][2] = {
        {1,10},{12,29},{30,33},{33,40},{40,64},{64,79},{79,84},{84,94},{94,96},
        {96,99},{99,105},{105,113},{116,122},{122,128},{128,151},{151,159},{160,165}};
    for (int i = 0; i < NSLICE; i++)
        if (c >= S[i][0] && c < S[i][1]) return i;
    return -1;  // MSE column
}

// ---------------- scratch (device globals; zero at module load) ------------
// finalize_kernel re-zeros everything it consumed, so no init kernel needed.
__device__ double   g_mse;
__device__ double   g_ce;
__device__ double   g_kld;
__device__ unsigned g_done;
__device__ unsigned g_mmdone;
__device__ unsigned g_min[10];
__device__ unsigned g_max[10];
__device__ int      g_male;
__device__ int      g_hist[2][10][NBINS];   // [sex][dim][bin]

__device__ __forceinline__ unsigned f2o(float f) {
    unsigned u = __float_as_uint(f);
    return (u & 0x80000000u) ? ~u : (u | 0x80000000u);
}
__device__ __forceinline__ float o2f(unsigned u) {
    return (u & 0x80000000u) ? __uint_as_float(u & 0x7FFFFFFFu)
                             : __uint_as_float(~u);
}
__device__ __forceinline__ unsigned ld_vol_u32(const unsigned* p) {
    unsigned v;
    asm volatile("ld.volatile.global.u32 %0, [%1];" : "=r"(v) : "l"(p));
    return v;
}

// ---------------- cp.async helpers -----------------------------------------
__device__ __forceinline__ void cp_async16(uint32_t s, const void* g) {
    asm volatile("cp.async.cg.shared.global [%0], [%1], 16;" :: "r"(s), "l"(g));
}
__device__ __forceinline__ void cp_commit() {
    asm volatile("cp.async.commit_group;" ::: "memory");
}
template <int N>
__device__ __forceinline__ void cp_wait() {
    asm volatile("cp.async.wait_group %0;" :: "n"(N) : "memory");
}

// ---------------- compile-time column handling (CE/MSE) --------------------
template <int C>
__device__ __forceinline__ void handle_col(float d, float t,
                                           float (&se)[NSLICE],
                                           float& dlab, float& msea) {
    constexpr int s = slice_of(C);
    if constexpr (s >= 0) {
        se[s] += __expf(d);
        dlab = __fmaf_rn(d, t, dlab);   // t is exact one-hot 0/1
    } else {
        float diff = d - t;
        msea = __fmaf_rn(diff, diff, msea);
    }
}

template <int CH>
__device__ __forceinline__ void issue_chunk(uint32_t sa_base, uint32_t sb_base,
                                            int tid,
                                            const float4* g0a, const float4* g1a,
                                            const float4* g0b, const float4* g1b) {
    constexpr uint32_t SOFF = (uint32_t)(CH % STAGES) * (ROWS_PB * NF * 16u);
    uint32_t o0 = SOFF + (uint32_t)tid * 16u;
    uint32_t o1 = SOFF + (uint32_t)(ROWS_PB + tid) * 16u;
    cp_async16(sa_base + o0, g0a + CH * NF);
    cp_async16(sa_base + o1, g1a + CH * NF);
    cp_async16(sb_base + o0, g0b + CH * NF);
    cp_async16(sb_base + o1, g1b + CH * NF);
    cp_commit();
}

template <int CH, int J>
__device__ __forceinline__ void compute_rec(const float4* sA, const float4* sB,
                                            int tid, float (&se)[NSLICE],
                                            float& dlab, float& msea) {
    if constexpr (J < NF) {
        float4 a = sA[tid * NF + J];
        float4 b = sB[tid * NF + J];
        constexpr int C = (CH * NF + J) * 4;
        handle_col<C + 0>(a.x, b.x, se, dlab, msea);
        handle_col<C + 1>(a.y, b.y, se, dlab, msea);
        handle_col<C + 2>(a.z, b.z, se, dlab, msea);
        handle_col<C + 3>(a.w, b.w, se, dlab, msea);
        compute_rec<CH, J + 1>(sA, sB, tid, se, dlab, msea);
    }
}

template <int CH>
__device__ __forceinline__ void pipe_loop(
        char* smem_raw, uint32_t sa_base, uint32_t sb_base, int tid,
        const float4* g0a, const float4* g1a,
        const float4* g0b, const float4* g1b,
        float (&se)[NSLICE], float& dlab, float& msea) {
    if constexpr (CH < NCH) {
        constexpr int OUT = (CH + 1 < NCH) ? 1 : 0;
        cp_wait<OUT>();
        __syncthreads();   // (a) chunk CH visible; (b) compute CH-1 done (ring reuse safe)
        if constexpr (CH + 2 < NCH)
            issue_chunk<CH + 2>(sa_base, sb_base, tid, g0a, g1a, g0b, g1b);
        const float4* sA = (const float4*)(smem_raw) + (CH % STAGES) * ROWS_PB * NF;
        const float4* sB = (const float4*)(smem_raw + HALF_PIPE) + (CH % STAGES) * ROWS_PB * NF;
        compute_rec<CH, 0>(sA, sB, tid, se, dlab, msea);
        pipe_loop<CH + 1>(smem_raw, sa_base, sb_base, tid,
                          g0a, g1a, g0b, g1b, se, dlab, msea);
    }
}

// minmax: update accumulators with compile-time column (4K+i) % 11; skip col 10
template <int K>
__device__ __forceinline__ void mm_f4(float4 v, float (&mn)[10], float (&mx)[10]) {
    constexpr int c0 = (4 * K + 0) % 11;
    constexpr int c1 = (4 * K + 1) % 11;
    constexpr int c2 = (4 * K + 2) % 11;
    constexpr int c3 = (4 * K + 3) % 11;
    if constexpr (c0 < 10) { mn[c0] = fminf(mn[c0], v.x); mx[c0] = fmaxf(mx[c0], v.x); }
    if constexpr (c1 < 10) { mn[c1] = fminf(mn[c1], v.y); mx[c1] = fmaxf(mx[c1], v.y); }
    if constexpr (c2 < 10) { mn[c2] = fminf(mn[c2], v.z); mx[c2] = fmaxf(mx[c2], v.z); }
    if constexpr (c3 < 10) { mn[c3] = fminf(mn[c3], v.w); mx[c3] = fmaxf(mx[c3], v.w); }
}

// ---------------- fused kernel ---------------------------------------------
__global__ void __launch_bounds__(ROWS_PB, 8) fused_kernel(
    const float* __restrict__ enc, const float* __restrict__ dec,
    const float* __restrict__ tru, const float* __restrict__ lab,
    int B) {

    __shared__ alignas(16) char smem_raw[PIPE_BYTES];   // 24 KB (pipe | packed hist)
    __shared__ float    s_ce[4], s_mse[4];
    __shared__ unsigned s_mn[10], s_mx[10];
    __shared__ int      s_male;

    int tid  = threadIdx.x;
    int wid  = tid >> 5;
    int lane = tid & 31;

    if (blockIdx.x >= PREPB) {
        // ================= main streaming block =================
        int base   = (blockIdx.x - PREPB) * ROWS_PB;
        int maxrow = min(ROWS_PB, B - base) - 1;
        bool valid = (base + tid < B);

        const float4* dp = (const float4*)(dec + (size_t)base * NCOLS);
        const float4* tp = (const float4*)(tru + (size_t)base * NCOLS);

        int r0 = min(tid >> 1, maxrow);
        int r1 = min((ROWS_PB + tid) >> 1, maxrow);
        int c  = tid & 1;
        const float4* g0a = dp + r0 * NF4 + c;
        const float4* g1a = dp + r1 * NF4 + c;
        const float4* g0b = tp + r0 * NF4 + c;
        const float4* g1b = tp + r1 * NF4 + c;

        uint32_t sa_base = (uint32_t)__cvta_generic_to_shared(smem_raw);
        uint32_t sb_base = sa_base + HALF_PIPE;

        float se[NSLICE];
#pragma unroll
        for (int i = 0; i < NSLICE; i++) se[i] = 0.0f;
        float dlab = 0.0f, msea = 0.0f;

        issue_chunk<0>(sa_base, sb_base, tid, g0a, g1a, g0b, g1b);
        issue_chunk<1>(sa_base, sb_base, tid, g0a, g1a, g0b, g1b);
        pipe_loop<0>(smem_raw, sa_base, sb_base, tid,
                     g0a, g1a, g0b, g1b, se, dlab, msea);

        float ce_row = 0.0f;
#pragma unroll
        for (int i = 0; i < NSLICE; i++) ce_row += __logf(se[i]);
        ce_row -= dlab;
        if (!valid) { ce_row = 0.0f; msea = 0.0f; }

        float cer = ce_row, mser = msea;
#pragma unroll
        for (int o = 16; o; o >>= 1) {
            cer  += __shfl_xor_sync(0xFFFFFFFFu, cer,  o);
            mser += __shfl_xor_sync(0xFFFFFFFFu, mser, o);
        }
        if (lane == 0) { s_ce[wid] = cer; s_mse[wid] = mser; }
        __syncthreads();

        if (tid == 0) {
            float c2 = 0.0f, m2 = 0.0f;
#pragma unroll
            for (int w = 0; w < 4; w++) { c2 += s_ce[w]; m2 += s_mse[w]; }
            atomicAdd(&g_ce,  (double)c2);
            atomicAdd(&g_mse, (double)m2);
        }
    } else {
        // ================= prep block: phase1 minmax, phase2 hist ==========
        if (tid < 10) { s_mn[tid] = 0xFFFFFFFFu; s_mx[tid] = 0u; }
        if (tid == 0) s_male = 0;

        // ---- phase 1: minmax + male over dense contiguous slice ----
        // thread t handles enc float4s [11t, 11t+11) = 4 full rows (static cols)
        int t = blockIdx.x * ROWS_PB + tid;          // 0 .. PREPB*128-1
        int nthreads_mm = (B + 3) / 4;               // threads with real work
        float mn[10], mx[10];
#pragma unroll
        for (int j = 0; j < 10; j++) {
            mn[j] = __int_as_float(0x7F800000);
            mx[j] = __int_as_float(0xFF800000);
        }
        int males = 0;
        if (t < nthreads_mm) {
            const float4* e4 = (const float4*)enc + (size_t)t * 11;
#pragma unroll
            for (int k = 0; k < 11; k++) {
                float4 v = __ldg(e4 + k);
                switch (k) {   // compile-time dispatch keeps cols constexpr
                    case 0:  mm_f4<0>(v, mn, mx); break;
                    case 1:  mm_f4<1>(v, mn, mx); break;
                    case 2:  mm_f4<2>(v, mn, mx); break;
                    case 3:  mm_f4<3>(v, mn, mx); break;
                    case 4:  mm_f4<4>(v, mn, mx); break;
                    case 5:  mm_f4<5>(v, mn, mx); break;
                    case 6:  mm_f4<6>(v, mn, mx); break;
                    case 7:  mm_f4<7>(v, mn, mx); break;
                    case 8:  mm_f4<8>(v, mn, mx); break;
                    case 9:  mm_f4<9>(v, mn, mx); break;
                    default: mm_f4<10>(v, mn, mx); break;
                }
            }
            float4 lv = __ldg((const float4*)lab + t);
            males = (lv.x < 0.5f) + (lv.y < 0.5f) + (lv.z < 0.5f) + (lv.w < 0.5f);
        }

        // zero packed hist while phase-1 values are live (no smem overlap)
        uint32_t* hsh = (uint32_t*)smem_raw;
        for (int i = tid; i < 10 * (NBINS / 2); i += ROWS_PB) hsh[i] = 0;
        __syncthreads();   // covers s_mn/s_mx init too

        // warp reduce
#pragma unroll
        for (int j = 0; j < 10; j++) {
            float a = mn[j], b = mx[j];
#pragma unroll
            for (int o = 16; o; o >>= 1) {
                a = fminf(a, __shfl_xor_sync(0xFFFFFFFFu, a, o));
                b = fmaxf(b, __shfl_xor_sync(0xFFFFFFFFu, b, o));
            }
            mn[j] = a; mx[j] = b;
        }
#pragma unroll
        for (int o = 16; o; o >>= 1)
            males += __shfl_xor_sync(0xFFFFFFFFu, males, o);

        if (lane == 0) {
#pragma unroll
            for (int j = 0; j < 10; j++) {
                atomicMin(&s_mn[j], f2o(mn[j]));
                atomicMax(&s_mx[j], f2o(mx[j]));
            }
            atomicAdd(&s_male, males);
        }
        __syncthreads();
        if (tid < 10) {
            atomicMin(&g_min[tid], s_mn[tid]);
            atomicMax(&g_max[tid], s_mx[tid]);
        }
        if (tid == 0) atomicAdd(&g_male, s_male);

        // ---- grid-subset barrier over the 512 prep blocks (all wave-1) ----
        __threadfence();
        __syncthreads();
        if (tid == 0) {
            atomicAdd(&g_mmdone, 1u);
            while (ld_vol_u32(&g_mmdone) < PREPB) __nanosleep(64);
        }
        __syncthreads();

        // ---- phase 2: histogram (one sex per block) ----
        int hb  = blockIdx.x;                // 0..PREPB-1
        int sex = hb / HB_PER_SEX;           // 0 = male, 1 = female
        int sub = hb % HB_PER_SEX;
        int rpb = (B + HB_PER_SEX - 1) / HB_PER_SEX;   // ~1024 << 65536
        int lo  = sub * rpb;
        int hi  = min(B, lo + rpb);

        float mnv[10], rng[10];
#pragma unroll
        for (int j = 0; j < 10; j++) {
            float a = o2f(__ldcg(&g_min[j]));
            float b = o2f(__ldcg(&g_max[j]));
            mnv[j] = a;
            rng[j] = b - a;
        }

        for (int row = lo + tid; row < hi; row += ROWS_PB) {
            int rsex = (__ldg(lab + row) < 0.5f) ? 0 : 1;
            if (rsex != sex) continue;
            const float* ep = enc + (size_t)row * 11;
#pragma unroll
            for (int j = 0; j < 10; j++) {
                float x  = __ldg(ep + j);
                // match jax fp32: t=(x-mn)/(mx-mn); idx=clip(floor(t*800),0,799)
                float tt = __fdiv_rn(x - mnv[j], rng[j]);
                float ft = floorf(__fmul_rn(tt, (float)NBINS));
                int idx = (int)ft;
                idx = max(0, min(NBINS - 1, idx));
                atomicAdd(&hsh[j * (NBINS / 2) + (idx >> 1)],
                          (idx & 1) ? 65536u : 1u);
            }
        }
        __syncthreads();

        int* gh = &g_hist[sex][0][0];
        for (int w = tid; w < 10 * (NBINS / 2); w += ROWS_PB) {
            uint32_t v = hsh[w];
            if (v) {
                int j  = w / (NBINS / 2);
                int b2 = (w - j * (NBINS / 2)) * 2;
                uint32_t lo16 = v & 0xFFFFu, hi16 = v >> 16;
                if (lo16) atomicAdd(&gh[j * NBINS + b2],     (int)lo16);
                if (hi16) atomicAdd(&gh[j * NBINS + b2 + 1], (int)hi16);
            }
        }
    }
}

// ---------------- finalize: multi-block JSD + combine + scratch reset ------
__global__ void __launch_bounds__(256) finalize_kernel(float* __restrict__ out, int B) {
    __shared__ double sred[8];

    int nmale = g_male;                 // read before any reset
    float nm_inv = 1.0f / (float)nmale;
    float nf_inv = 1.0f / (float)(B - nmale);
    const float eps = 1e-12f;

    float acc = 0.0f;
    int* hm = &g_hist[0][0][0];
    int* hf = &g_hist[1][0][0];
    for (int i = blockIdx.x * 256 + threadIdx.x; i < 10 * NBINS;
         i += FIN_BLOCKS * 256) {
        int a = hm[i], b = hf[i];
        hm[i] = 0; hf[i] = 0;           // re-zero for next replay
        float m = (float)a * nm_inv;
        float f = (float)b * nf_inv;
        float mid = 0.5f * (m + f);
        float inv_mid = 1.0f / (mid + eps);
        if (m > 0.0f) acc += m * logf((m + eps) * inv_mid);
        if (f > 0.0f) acc += f * logf((f + eps) * inv_mid);
    }

    double d = (double)acc;
#pragma unroll
    for (int o = 16; o; o >>= 1)
        d += __shfl_xor_sync(0xFFFFFFFFu, d, o);
    int wid = threadIdx.x >> 5;
    if ((threadIdx.x & 31) == 0) sred[wid] = d;
    __syncthreads();

    if (threadIdx.x == 0) {
        double s = 0.0;
#pragma unroll
        for (int w = 0; w < 8; w++) s += sred[w];
        atomicAdd(&g_kld, s);
        __threadfence();
        unsigned ticket = atomicAdd(&g_done, 1u);
        if (ticket == FIN_BLOCKS - 1) {
            double kld = 0.5 * atomicAdd(&g_kld, 0.0);
            double mse = g_mse / (double)B;
            double ce  = g_ce  / (double)B;
            out[0] = (float)((1.0 - RATIO_JSD) * (mse + ce) + RATIO_JSD * kld);
            out[1] = (float)mse;
            out[2] = (float)ce;
            out[3] = (float)(RATIO_JSD * kld);
            // reset scalar scratch for the next replay
            g_mse = 0.0; g_ce = 0.0; g_kld = 0.0;
            g_male = 0; g_done = 0u; g_mmdone = 0u;
#pragma unroll
            for (int j = 0; j < 10; j++) {
                g_min[j] = 0xFFFFFFFFu;
                g_max[j] = 0u;
            }
        }
    }
}

// ---------------- launch ----------------------------------------------------
extern "C" void kernel_launch(void* const* d_in, const int* in_sizes, int n_in,
                              void* d_out, int out_size) {
    const float* enc = (const float*)d_in[0];   // [B,11]
    const float* dec = (const float*)d_in[1];   // [B,168]
    const float* tru = (const float*)d_in[2];   // [B,168]
    const float* lab = (const float*)d_in[3];   // [B,1]
    int B = in_sizes[3];

    int mainb = (B + ROWS_PB - 1) / ROWS_PB;
    fused_kernel<<<PREPB + mainb, ROWS_PB>>>(enc, dec, tru, lab, B);

    finalize_kernel<<<FIN_BLOCKS, 256>>>((float*)d_out, B);
}

// round 17
// speedup vs baseline: 1.0727x; 1.0727x over previous
#include <cuda_runtime.h>
#include <cstdint>

// ---------------------------------------------------------------------------
// MultiLoss_JSD: fused MSE + 17-head CE + histogram JSD
// B = 262144 rows; decoded/true: [B,168] f32; encoded: [B,11] f32; label: [B,1] f32
// out: 4 floats [multi, mse, ce, 0.1*kld]
//
// Graph: minmax_kernel (coalesced enc min/max + male count)
//        -> fused_kernel (hist blocks FIRST for overlap, then main stream blocks)
//        -> finalize_kernel (one bin/thread JSD + combine + scratch reset)
// ---------------------------------------------------------------------------

#define NSLICE 17
#define NBINS  800
#define NCOLS  168
#define NF4    42          // float4s per row
#define NF     2           // float4s per chunk per row
#define NCH    21          // 21 chunks * 8 cols = 168
#define STAGES 3
#define ROWS_PB 128
#define RATIO_JSD 0.1
#define FIN_BLOCKS 32
#define HB_PER_SEX 256     // hist blocks per sex (row quota ~1024 << 65536)
#define HISTB (2 * HB_PER_SEX)

#define PIPE_BYTES (STAGES * ROWS_PB * NF * 16 * 2)   // 24576
#define HALF_PIPE  (STAGES * ROWS_PB * NF * 16)       // 12288

__host__ __device__ constexpr int slice_of(int c) {
    const int S[NSLICE][2] = {
        {1,10},{12,29},{30,33},{33,40},{40,64},{64,79},{79,84},{84,94},{94,96},
        {96,99},{99,105},{105,113},{116,122},{122,128},{128,151},{151,159},{160,165}};
    for (int i = 0; i < NSLICE; i++)
        if (c >= S[i][0] && c < S[i][1]) return i;
    return -1;  // MSE column
}

// ---------------- scratch (device globals; zero at module load) ------------
// finalize_kernel re-zeros everything it consumed, so no init kernel needed.
__device__ double   g_mse;
__device__ double   g_ce;
__device__ double   g_kld;
__device__ unsigned g_done;
__device__ unsigned g_min[10];
__device__ unsigned g_max[10];
__device__ int      g_male;
__device__ int      g_hist[2][10][NBINS];   // [sex][dim][bin]

__device__ __forceinline__ unsigned f2o(float f) {
    unsigned u = __float_as_uint(f);
    return (u & 0x80000000u) ? ~u : (u | 0x80000000u);
}
__device__ __forceinline__ float o2f(unsigned u) {
    return (u & 0x80000000u) ? __uint_as_float(u & 0x7FFFFFFFu)
                             : __uint_as_float(~u);
}

// ---------------- cp.async helpers -----------------------------------------
__device__ __forceinline__ void cp_async16(uint32_t s, const void* g) {
    asm volatile("cp.async.cg.shared.global [%0], [%1], 16;" :: "r"(s), "l"(g));
}
__device__ __forceinline__ void cp_commit() {
    asm volatile("cp.async.commit_group;" ::: "memory");
}
template <int N>
__device__ __forceinline__ void cp_wait() {
    asm volatile("cp.async.wait_group %0;" :: "n"(N) : "memory");
}

// ---------------- compile-time column handling (CE/MSE) --------------------
template <int C>
__device__ __forceinline__ void handle_col(float d, float t,
                                           float (&se)[NSLICE],
                                           float& dlab, float& msea) {
    constexpr int s = slice_of(C);
    if constexpr (s >= 0) {
        se[s] += __expf(d);
        dlab = __fmaf_rn(d, t, dlab);   // t is exact one-hot 0/1
    } else {
        float diff = d - t;
        msea = __fmaf_rn(diff, diff, msea);
    }
}

template <int CH>
__device__ __forceinline__ void issue_chunk(uint32_t sa_base, uint32_t sb_base,
                                            int tid,
                                            const float4* g0a, const float4* g1a,
                                            const float4* g0b, const float4* g1b) {
    constexpr uint32_t SOFF = (uint32_t)(CH % STAGES) * (ROWS_PB * NF * 16u);
    uint32_t o0 = SOFF + (uint32_t)tid * 16u;
    uint32_t o1 = SOFF + (uint32_t)(ROWS_PB + tid) * 16u;
    cp_async16(sa_base + o0, g0a + CH * NF);
    cp_async16(sa_base + o1, g1a + CH * NF);
    cp_async16(sb_base + o0, g0b + CH * NF);
    cp_async16(sb_base + o1, g1b + CH * NF);
    cp_commit();
}

template <int CH, int J>
__device__ __forceinline__ void compute_rec(const float4* sA, const float4* sB,
                                            int tid, float (&se)[NSLICE],
                                            float& dlab, float& msea) {
    if constexpr (J < NF) {
        float4 a = sA[tid * NF + J];
        float4 b = sB[tid * NF + J];
        constexpr int C = (CH * NF + J) * 4;
        handle_col<C + 0>(a.x, b.x, se, dlab, msea);
        handle_col<C + 1>(a.y, b.y, se, dlab, msea);
        handle_col<C + 2>(a.z, b.z, se, dlab, msea);
        handle_col<C + 3>(a.w, b.w, se, dlab, msea);
        compute_rec<CH, J + 1>(sA, sB, tid, se, dlab, msea);
    }
}

template <int CH>
__device__ __forceinline__ void pipe_loop(
        char* smem_raw, uint32_t sa_base, uint32_t sb_base, int tid,
        const float4* g0a, const float4* g1a,
        const float4* g0b, const float4* g1b,
        float (&se)[NSLICE], float& dlab, float& msea) {
    if constexpr (CH < NCH) {
        constexpr int OUT = (CH + 1 < NCH) ? 1 : 0;
        cp_wait<OUT>();
        __syncthreads();   // (a) chunk CH visible; (b) compute CH-1 done (ring reuse safe)
        if constexpr (CH + 2 < NCH)
            issue_chunk<CH + 2>(sa_base, sb_base, tid, g0a, g1a, g0b, g1b);
        const float4* sA = (const float4*)(smem_raw) + (CH % STAGES) * ROWS_PB * NF;
        const float4* sB = (const float4*)(smem_raw + HALF_PIPE) + (CH % STAGES) * ROWS_PB * NF;
        compute_rec<CH, 0>(sA, sB, tid, se, dlab, msea);
        pipe_loop<CH + 1>(smem_raw, sa_base, sb_base, tid,
                          g0a, g1a, g0b, g1b, se, dlab, msea);
    }
}

// minmax: update accumulators with compile-time column (4K+i) % 11; skip col 10
template <int K>
__device__ __forceinline__ void mm_f4(float4 v, float (&mn)[10], float (&mx)[10]) {
    constexpr int c0 = (4 * K + 0) % 11;
    constexpr int c1 = (4 * K + 1) % 11;
    constexpr int c2 = (4 * K + 2) % 11;
    constexpr int c3 = (4 * K + 3) % 11;
    if constexpr (c0 < 10) { mn[c0] = fminf(mn[c0], v.x); mx[c0] = fmaxf(mx[c0], v.x); }
    if constexpr (c1 < 10) { mn[c1] = fminf(mn[c1], v.y); mx[c1] = fmaxf(mx[c1], v.y); }
    if constexpr (c2 < 10) { mn[c2] = fminf(mn[c2], v.z); mx[c2] = fmaxf(mx[c2], v.z); }
    if constexpr (c3 < 10) { mn[c3] = fminf(mn[c3], v.w); mx[c3] = fmaxf(mx[c3], v.w); }
}

// ---------------- pre-pass: enc min/max + male count (fully coalesced) -----
// Thread t owns enc float4s [11t, 11t+11) = exactly 4 rows; columns are
// compile-time via (4k+i) mod 11. lab read as one float4 (4 rows).
__global__ void __launch_bounds__(256) minmax_kernel(
    const float* __restrict__ enc, const float* __restrict__ lab, int B) {

    __shared__ unsigned s_mn[10], s_mx[10];
    __shared__ int s_male;
    int tid = threadIdx.x;
    if (tid < 10) { s_mn[tid] = 0xFFFFFFFFu; s_mx[tid] = 0u; }
    if (tid == 0) s_male = 0;
    __syncthreads();

    float mn[10], mx[10];
#pragma unroll
    for (int j = 0; j < 10; j++) {
        mn[j] = __int_as_float(0x7F800000);
        mx[j] = __int_as_float(0xFF800000);
    }
    int males = 0;

    int t = blockIdx.x * 256 + tid;
    if (t < (B + 3) / 4) {
        const float4* e4 = (const float4*)enc + (size_t)t * 11;
#pragma unroll
        for (int k = 0; k < 11; k++) {
            float4 v = __ldg(e4 + k);
            switch (k) {
                case 0:  mm_f4<0>(v, mn, mx); break;
                case 1:  mm_f4<1>(v, mn, mx); break;
                case 2:  mm_f4<2>(v, mn, mx); break;
                case 3:  mm_f4<3>(v, mn, mx); break;
                case 4:  mm_f4<4>(v, mn, mx); break;
                case 5:  mm_f4<5>(v, mn, mx); break;
                case 6:  mm_f4<6>(v, mn, mx); break;
                case 7:  mm_f4<7>(v, mn, mx); break;
                case 8:  mm_f4<8>(v, mn, mx); break;
                case 9:  mm_f4<9>(v, mn, mx); break;
                default: mm_f4<10>(v, mn, mx); break;
            }
        }
        float4 lv = __ldg((const float4*)lab + t);
        males = (lv.x < 0.5f) + (lv.y < 0.5f) + (lv.z < 0.5f) + (lv.w < 0.5f);
    }

#pragma unroll
    for (int j = 0; j < 10; j++) {
        float a = mn[j], b = mx[j];
#pragma unroll
        for (int o = 16; o; o >>= 1) {
            a = fminf(a, __shfl_xor_sync(0xFFFFFFFFu, a, o));
            b = fmaxf(b, __shfl_xor_sync(0xFFFFFFFFu, b, o));
        }
        mn[j] = a; mx[j] = b;
    }
#pragma unroll
    for (int o = 16; o; o >>= 1)
        males += __shfl_xor_sync(0xFFFFFFFFu, males, o);

    if ((tid & 31) == 0) {
#pragma unroll
        for (int j = 0; j < 10; j++) {
            atomicMin(&s_mn[j], f2o(mn[j]));
            atomicMax(&s_mx[j], f2o(mx[j]));
        }
        atomicAdd(&s_male, males);
    }
    __syncthreads();
    if (tid < 10) {
        atomicMin(&g_min[tid], s_mn[tid]);
        atomicMax(&g_max[tid], s_mx[tid]);
    }
    if (tid == 0) atomicAdd(&g_male, s_male);
}

// ---------------- fused: histogram blocks FIRST, then main stream ----------
__global__ void __launch_bounds__(ROWS_PB, 8) fused_kernel(
    const float* __restrict__ enc, const float* __restrict__ dec,
    const float* __restrict__ tru, const float* __restrict__ lab,
    int B) {

    __shared__ alignas(16) char smem_raw[PIPE_BYTES];   // 24 KB (pipe | packed hist)
    __shared__ float s_ce[4], s_mse[4];

    int tid  = threadIdx.x;
    int wid  = tid >> 5;
    int lane = tid & 31;

    if (blockIdx.x >= HISTB) {
        // ================= main streaming block =================
        int base   = (blockIdx.x - HISTB) * ROWS_PB;
        int maxrow = min(ROWS_PB, B - base) - 1;
        bool valid = (base + tid < B);

        const float4* dp = (const float4*)(dec + (size_t)base * NCOLS);
        const float4* tp = (const float4*)(tru + (size_t)base * NCOLS);

        int r0 = min(tid >> 1, maxrow);
        int r1 = min((ROWS_PB + tid) >> 1, maxrow);
        int c  = tid & 1;
        const float4* g0a = dp + r0 * NF4 + c;
        const float4* g1a = dp + r1 * NF4 + c;
        const float4* g0b = tp + r0 * NF4 + c;
        const float4* g1b = tp + r1 * NF4 + c;

        uint32_t sa_base = (uint32_t)__cvta_generic_to_shared(smem_raw);
        uint32_t sb_base = sa_base + HALF_PIPE;

        float se[NSLICE];
#pragma unroll
        for (int i = 0; i < NSLICE; i++) se[i] = 0.0f;
        float dlab = 0.0f, msea = 0.0f;

        issue_chunk<0>(sa_base, sb_base, tid, g0a, g1a, g0b, g1b);
        issue_chunk<1>(sa_base, sb_base, tid, g0a, g1a, g0b, g1b);
        pipe_loop<0>(smem_raw, sa_base, sb_base, tid,
                     g0a, g1a, g0b, g1b, se, dlab, msea);

        float ce_row = 0.0f;
#pragma unroll
        for (int i = 0; i < NSLICE; i++) ce_row += __logf(se[i]);
        ce_row -= dlab;
        if (!valid) { ce_row = 0.0f; msea = 0.0f; }

        float cer = ce_row, mser = msea;
#pragma unroll
        for (int o = 16; o; o >>= 1) {
            cer  += __shfl_xor_sync(0xFFFFFFFFu, cer,  o);
            mser += __shfl_xor_sync(0xFFFFFFFFu, mser, o);
        }
        if (lane == 0) { s_ce[wid] = cer; s_mse[wid] = mser; }
        __syncthreads();

        if (tid == 0) {
            float c2 = 0.0f, m2 = 0.0f;
#pragma unroll
            for (int w = 0; w < 4; w++) { c2 += s_ce[w]; m2 += s_mse[w]; }
            atomicAdd(&g_ce,  (double)c2);
            atomicAdd(&g_mse, (double)m2);
        }
    } else {
        // ================= histogram block (first wave, overlaps main) =====
        // packed 2x16-bit counters: 10 dims x 400 words (=800 bins), 16 KB
        uint32_t* hsh = (uint32_t*)smem_raw;
        for (int i = tid; i < 10 * (NBINS / 2); i += ROWS_PB) hsh[i] = 0;
        __syncthreads();

        int hb  = blockIdx.x;                // 0..HISTB-1
        int sex = hb / HB_PER_SEX;           // 0 = male, 1 = female
        int sub = hb % HB_PER_SEX;
        int rpb = (B + HB_PER_SEX - 1) / HB_PER_SEX;   // ~1024 << 65536
        int lo  = sub * rpb;
        int hi  = min(B, lo + rpb);

        float mnv[10], rng[10];
#pragma unroll
        for (int j = 0; j < 10; j++) {
            mnv[j] = o2f(g_min[j]);
            rng[j] = o2f(g_max[j]) - mnv[j];
        }

        for (int row = lo + tid; row < hi; row += ROWS_PB) {
            int rsex = (__ldg(lab + row) < 0.5f) ? 0 : 1;
            if (rsex != sex) continue;
            const float* ep = enc + (size_t)row * 11;
#pragma unroll
            for (int j = 0; j < 10; j++) {
                float x  = __ldg(ep + j);
                // match jax fp32: t=(x-mn)/(mx-mn); idx=clip(floor(t*800),0,799)
                float t  = __fdiv_rn(x - mnv[j], rng[j]);
                float ft = floorf(__fmul_rn(t, (float)NBINS));
                int idx = (int)ft;
                idx = max(0, min(NBINS - 1, idx));
                atomicAdd(&hsh[j * (NBINS / 2) + (idx >> 1)],
                          (idx & 1) ? 65536u : 1u);
            }
        }
        __syncthreads();

        int* gh = &g_hist[sex][0][0];
        for (int w = tid; w < 10 * (NBINS / 2); w += ROWS_PB) {
            uint32_t v = hsh[w];
            if (v) {
                int j  = w / (NBINS / 2);
                int b2 = (w - j * (NBINS / 2)) * 2;
                uint32_t lo16 = v & 0xFFFFu, hi16 = v >> 16;
                if (lo16) atomicAdd(&gh[j * NBINS + b2],     (int)lo16);
                if (hi16) atomicAdd(&gh[j * NBINS + b2 + 1], (int)hi16);
            }
        }
    }
}

// ---------------- finalize: one bin/thread JSD + combine + scratch reset ---
__global__ void __launch_bounds__(256) finalize_kernel(float* __restrict__ out, int B) {
    __shared__ double sred[8];

    int nmale = g_male;                 // read before any reset
    float nm_inv = 1.0f / (float)nmale;
    float nf_inv = 1.0f / (float)(B - nmale);
    const float eps = 1e-12f;

    float acc = 0.0f;
    int* hm = &g_hist[0][0][0];
    int* hf = &g_hist[1][0][0];
    int i = blockIdx.x * 256 + threadIdx.x;   // 8192 threads, 8000 bins
    if (i < 10 * NBINS) {
        int a = hm[i], b = hf[i];
        hm[i] = 0; hf[i] = 0;           // re-zero for next replay
        float m = (float)a * nm_inv;
        float f = (float)b * nf_inv;
        float mid = 0.5f * (m + f);
        float inv_mid = 1.0f / (mid + eps);
        if (m > 0.0f) acc += m * logf((m + eps) * inv_mid);
        if (f > 0.0f) acc += f * logf((f + eps) * inv_mid);
    }

    double d = (double)acc;
#pragma unroll
    for (int o = 16; o; o >>= 1)
        d += __shfl_xor_sync(0xFFFFFFFFu, d, o);
    int wid = threadIdx.x >> 5;
    if ((threadIdx.x & 31) == 0) sred[wid] = d;
    __syncthreads();

    if (threadIdx.x == 0) {
        double s = 0.0;
#pragma unroll
        for (int w = 0; w < 8; w++) s += sred[w];
        atomicAdd(&g_kld, s);
        __threadfence();
        unsigned ticket = atomicAdd(&g_done, 1u);
        if (ticket == FIN_BLOCKS - 1) {
            double kld = 0.5 * atomicAdd(&g_kld, 0.0);
            double mse = g_mse / (double)B;
            double ce  = g_ce  / (double)B;
            out[0] = (float)((1.0 - RATIO_JSD) * (mse + ce) + RATIO_JSD * kld);
            out[1] = (float)mse;
            out[2] = (float)ce;
            out[3] = (float)(RATIO_JSD * kld);
            // reset scalar scratch for the next replay
            g_mse = 0.0; g_ce = 0.0; g_kld = 0.0;
            g_male = 0; g_done = 0u;
#pragma unroll
            for (int j = 0; j < 10; j++) {
                g_min[j] = 0xFFFFFFFFu;
                g_max[j] = 0u;
            }
        }
    }
}

// ---------------- launch ----------------------------------------------------
extern "C" void kernel_launch(void* const* d_in, const int* in_sizes, int n_in,
                              void* d_out, int out_size) {
    const float* enc = (const float*)d_in[0];   // [B,11]
    const float* dec = (const float*)d_in[1];   // [B,168]
    const float* tru = (const float*)d_in[2];   // [B,168]
    const float* lab = (const float*)d_in[3];   // [B,1]
    int B = in_sizes[3];

    int mmb = ((B + 3) / 4 + 255) / 256;        // 256 blocks for B=262144
    minmax_kernel<<<mmb, 256>>>(enc, lab, B);

    int mainb = (B + ROWS_PB - 1) / ROWS_PB;
    fused_kernel<<<HISTB + mainb, ROWS_PB>>>(enc, dec, tru, lab, B);

    finalize_kernel<<<FIN_BLOCKS, 256>>>((float*)d_out, B);
}